// round 1
// baseline (speedup 1.0000x reference)
#include <cuda_runtime.h>
#include <math.h>

#define BSZ   8
#define SEQ   512
#define DIM   768
#define NP    32
#define PE    200
#define EMB   128
#define VOCAB 30522
#define SPAN  20
#define NBP   (BSZ*NP)       // 256
#define NROWS (NBP*SPAN)     // 5120

// ---------------- scratch (device globals; no allocation allowed) ----------------
__device__ float g_G[NBP * 2 * DIM];      // gathered [lh|rh] rows   256 x 1536
__device__ float g_u[NBP * DIM];          // u = G @ W1[0:1536]      256 x 768
__device__ float g_posW[SPAN * DIM];      // pos_emb @ W1[1536:]      20 x 768
__device__ float g_h1[NROWS * DIM];       // LN(gelu(x@W1+b1))      5120 x 768
__device__ float g_h2[NROWS * DIM];       // LN(gelu(h1@W2+b2))     5120 x 768
__device__ float g_h3[NROWS * EMB];       // h2@Wp + bp             5120 x 128

// ---------------- gather span endpoints ----------------
__global__ void gather_kernel(const float* __restrict__ hs, const int* __restrict__ pairs) {
    int bp = blockIdx.x;              // 0..255
    int b = bp / NP;
    int li = pairs[bp * 2 + 0];
    int ri = pairs[bp * 2 + 1];
    const float* lrow = hs + ((long)b * SEQ + li) * DIM;
    const float* rrow = hs + ((long)b * SEQ + ri) * DIM;
    float* gl = g_G + (long)bp * (2 * DIM);
    for (int i = threadIdx.x; i < DIM; i += blockDim.x) {
        gl[i]       = lrow[i];
        gl[DIM + i] = rrow[i];
    }
}

// ---------------- generic tiled fp32 GEMM: C = A @ B (+bias), B optionally [N,K] ----------------
template <bool TRANS_B, bool HAS_BIAS>
__global__ void gemm_kernel(const float* __restrict__ A, const float* __restrict__ B,
                            const float* __restrict__ bias, float* __restrict__ C,
                            int M, int N, int K) {
    const int BM = 64, BN = 64, BK = 16;
    __shared__ __align__(16) float As[BK][BM + 4];
    __shared__ __align__(16) float Bs[BK][BN + 4];

    int bm = blockIdx.y * BM;
    int bn = blockIdx.x * BN;
    int tid = threadIdx.x;            // 256 threads
    int tx = tid % 16;                // N direction
    int ty = tid / 16;                // M direction

    float acc[4][4] = {};

    for (int k0 = 0; k0 < K; k0 += BK) {
        // --- load A tile (64 x 16), each thread 4 consecutive k of one row ---
        {
            int idx = tid * 4;
            int m = idx / BK;
            int k = idx % BK;
            int gm = bm + m;
            const float* ap = A + (long)gm * K + k0 + k;
#pragma unroll
            for (int i = 0; i < 4; i++) {
                int gk = k0 + k + i;
                As[k + i][m] = (gm < M && gk < K) ? ap[i] : 0.f;
            }
        }
        // --- load B tile into Bs[k][n] ---
        if (!TRANS_B) {
            int idx = tid * 4;
            int k = idx / BN;
            int n = idx % BN;
            int gk = k0 + k;
            const float* bpr = B + (long)gk * N + bn + n;
#pragma unroll
            for (int i = 0; i < 4; i++) {
                int gn = bn + n + i;
                Bs[k][n + i] = (gk < K && gn < N) ? bpr[i] : 0.f;
            }
        } else {
            int idx = tid * 4;
            int n = idx / BK;
            int k = idx % BK;
            int gn = bn + n;
            const float* bpr = B + (long)gn * K + k0 + k;
#pragma unroll
            for (int i = 0; i < 4; i++) {
                int gk = k0 + k + i;
                Bs[k + i][n] = (gn < N && gk < K) ? bpr[i] : 0.f;
            }
        }
        __syncthreads();

#pragma unroll
        for (int kk = 0; kk < BK; kk++) {
            float4 a4 = *reinterpret_cast<const float4*>(&As[kk][ty * 4]);
            float4 b4 = *reinterpret_cast<const float4*>(&Bs[kk][tx * 4]);
            float a[4] = {a4.x, a4.y, a4.z, a4.w};
            float b[4] = {b4.x, b4.y, b4.z, b4.w};
#pragma unroll
            for (int i = 0; i < 4; i++)
#pragma unroll
                for (int j = 0; j < 4; j++)
                    acc[i][j] = fmaf(a[i], b[j], acc[i][j]);
        }
        __syncthreads();
    }

#pragma unroll
    for (int i = 0; i < 4; i++) {
        int gm = bm + ty * 4 + i;
        if (gm >= M) continue;
#pragma unroll
        for (int j = 0; j < 4; j++) {
            int gn = bn + tx * 4 + j;
            if (gn < N) {
                float v = acc[i][j];
                if (HAS_BIAS) v += bias[gn];
                C[(long)gm * N + gn] = v;
            }
        }
    }
}

// ---------------- exact BERT gelu ----------------
__device__ __forceinline__ float gelu_exact(float x) {
    return 0.5f * x * (1.f + erff(x * 0.70710678118654752f));
}

// ---------------- fused add + gelu + layernorm -> h1 ----------------
__global__ void fuse1_kernel(const float* __restrict__ b1, const float* __restrict__ g1,
                             const float* __restrict__ be1) {
    int row = blockIdx.x;             // 0..5119
    int bp = row / SPAN;
    int l = row % SPAN;
    __shared__ float s[DIM];
    __shared__ float red[256];
    int t = threadIdx.x;

    const float* up = g_u + (long)bp * DIM;
    const float* pp = g_posW + (long)l * DIM;

    float local = 0.f;
    for (int i = t; i < DIM; i += 256) {
        float x = up[i] + pp[i] + b1[i];
        float g = gelu_exact(x);
        s[i] = g;
        local += g;
    }
    red[t] = local;
    __syncthreads();
    for (int off = 128; off > 0; off >>= 1) {
        if (t < off) red[t] += red[t + off];
        __syncthreads();
    }
    float mu = red[0] * (1.f / DIM);
    __syncthreads();

    float lv = 0.f;
    for (int i = t; i < DIM; i += 256) {
        float d = s[i] - mu;
        lv += d * d;
    }
    red[t] = lv;
    __syncthreads();
    for (int off = 128; off > 0; off >>= 1) {
        if (t < off) red[t] += red[t + off];
        __syncthreads();
    }
    float rstd = rsqrtf(red[0] * (1.f / DIM) + 1e-12f);

    float* op = g_h1 + (long)row * DIM;
    for (int i = t; i < DIM; i += 256)
        op[i] = (s[i] - mu) * rstd * g1[i] + be1[i];
}

// ---------------- fused gelu + layernorm, in place on g_h2 ----------------
__global__ void fuse2_kernel(const float* __restrict__ g2, const float* __restrict__ be2) {
    int row = blockIdx.x;
    __shared__ float s[DIM];
    __shared__ float red[256];
    int t = threadIdx.x;

    float* rp = g_h2 + (long)row * DIM;
    float local = 0.f;
    for (int i = t; i < DIM; i += 256) {
        float g = gelu_exact(rp[i]);
        s[i] = g;
        local += g;
    }
    red[t] = local;
    __syncthreads();
    for (int off = 128; off > 0; off >>= 1) {
        if (t < off) red[t] += red[t + off];
        __syncthreads();
    }
    float mu = red[0] * (1.f / DIM);
    __syncthreads();

    float lv = 0.f;
    for (int i = t; i < DIM; i += 256) {
        float d = s[i] - mu;
        lv += d * d;
    }
    red[t] = lv;
    __syncthreads();
    for (int off = 128; off > 0; off >>= 1) {
        if (t < off) red[t] += red[t + off];
        __syncthreads();
    }
    float rstd = rsqrtf(red[0] * (1.f / DIM) + 1e-12f);

    for (int i = t; i < DIM; i += 256)
        rp[i] = (s[i] - mu) * rstd * g2[i] + be2[i];
}

// ---------------- launch ----------------
extern "C" void kernel_launch(void* const* d_in, const int* in_sizes, int n_in,
                              void* d_out, int out_size) {
    const float* hs    = (const float*)d_in[0];
    const int*   pairs = (const int*)  d_in[1];
    const float* pos   = (const float*)d_in[2];
    const float* W1    = (const float*)d_in[3];
    const float* b1    = (const float*)d_in[4];
    const float* g1    = (const float*)d_in[5];
    const float* be1   = (const float*)d_in[6];
    const float* W2    = (const float*)d_in[7];
    const float* b2    = (const float*)d_in[8];
    const float* g2    = (const float*)d_in[9];
    const float* be2   = (const float*)d_in[10];
    const float* Wp    = (const float*)d_in[11];
    const float* bpv   = (const float*)d_in[12];
    const float* Wdec  = (const float*)d_in[13];
    float* out = (float*)d_out;

    float *pG, *pu, *pposW, *ph1, *ph2, *ph3;
    cudaGetSymbolAddress((void**)&pG,    g_G);
    cudaGetSymbolAddress((void**)&pu,    g_u);
    cudaGetSymbolAddress((void**)&pposW, g_posW);
    cudaGetSymbolAddress((void**)&ph1,   g_h1);
    cudaGetSymbolAddress((void**)&ph2,   g_h2);
    cudaGetSymbolAddress((void**)&ph3,   g_h3);

    // 1. gather span endpoint rows -> G [256, 1536]
    gather_kernel<<<NBP, 256>>>(hs, pairs);

    // 2. u = G @ W1[0:1536,:]   (256 x 768, K=1536)
    gemm_kernel<false, false><<<dim3(DIM / 64, NBP / 64), 256>>>(pG, W1, nullptr, pu,
                                                                 NBP, DIM, 2 * DIM);
    // 3. posW = pos_emb @ W1[1536:,:]   (20 x 768, K=200)
    gemm_kernel<false, false><<<dim3(DIM / 64, 1), 256>>>(pos, W1 + (long)2 * DIM * DIM,
                                                          nullptr, pposW, SPAN, DIM, PE);
    // 4. h1 = LN(gelu(u + posW + b1))
    fuse1_kernel<<<NROWS, 256>>>(b1, g1, be1);

    // 5. h2pre = h1 @ W2 + b2
    gemm_kernel<false, true><<<dim3(DIM / 64, NROWS / 64), 256>>>(ph1, W2, b2, ph2,
                                                                  NROWS, DIM, DIM);
    // 6. h2 = LN(gelu(h2pre)) in place
    fuse2_kernel<<<NROWS, 256>>>(g2, be2);

    // 7. h3 = h2 @ Wp + bp   (5120 x 128, K=768)
    gemm_kernel<false, true><<<dim3(EMB / 64, NROWS / 64), 256>>>(ph2, Wp, bpv, ph3,
                                                                  NROWS, EMB, DIM);
    // 8. out = h3 @ Wdec^T   (5120 x 30522, K=128)
    gemm_kernel<true, false><<<dim3((VOCAB + 63) / 64, NROWS / 64), 256>>>(ph3, Wdec, nullptr,
                                                                           out, NROWS, VOCAB, EMB);
}

// round 3
// speedup vs baseline: 2.1161x; 2.1161x over previous
#include <cuda_runtime.h>
#include <cuda_bf16.h>
#include <math.h>
#include <stdint.h>

#define BSZ   8
#define SEQ   512
#define DIM   768
#define NP    32
#define PE    200
#define EMB   128
#define VOCAB 30522
#define SPAN  20
#define NBP   (BSZ*NP)       // 256
#define NROWS (NBP*SPAN)     // 5120

#define NTILE_N 120          // N tiles of 256 cols -> covers 30720 (pad from 30522)
#define NTILE_M 40           // M tiles of 128 rows
#define BROWS   (NTILE_N*256)  // 30720 padded B rows

// ---------------- scratch ----------------
__device__ float g_G[NBP * 2 * DIM];
__device__ float g_u[NBP * DIM];
__device__ float g_posW[SPAN * DIM];
__device__ float g_h1[NROWS * DIM];
__device__ float g_h2[NROWS * DIM];
__device__ float g_h3[NROWS * EMB];
__device__ __nv_bfloat16 g_Ahi[NROWS * EMB];
__device__ __nv_bfloat16 g_Alo[NROWS * EMB];
__device__ __nv_bfloat16 g_Bhi[BROWS * EMB];
__device__ __nv_bfloat16 g_Blo[BROWS * EMB];

// ---------------- helpers ----------------
__device__ __forceinline__ uint32_t smem_to_u32(const void* p) {
    uint32_t a;
    asm("{ .reg .u64 t; cvta.to.shared.u64 t, %1; cvt.u32.u64 %0, t; }" : "=r"(a) : "l"(p));
    return a;
}
__device__ __forceinline__ void cp_async16(uint32_t s, const void* g) {
    asm volatile("cp.async.cg.shared.global [%0], [%1], 16;" :: "r"(s), "l"(g));
}
__device__ __forceinline__ void ldmx4(uint32_t* r, uint32_t addr) {
    asm volatile("ldmatrix.sync.aligned.m8n8.x4.shared.b16 {%0,%1,%2,%3}, [%4];"
        : "=r"(r[0]), "=r"(r[1]), "=r"(r[2]), "=r"(r[3]) : "r"(addr));
}
__device__ __forceinline__ void mma_bf16(float* c, const uint32_t* a, uint32_t b0, uint32_t b1) {
    asm volatile("mma.sync.aligned.m16n8k16.row.col.f32.bf16.bf16.f32 "
        "{%0,%1,%2,%3}, {%4,%5,%6,%7}, {%8,%9}, {%0,%1,%2,%3};"
        : "+f"(c[0]), "+f"(c[1]), "+f"(c[2]), "+f"(c[3])
        : "r"(a[0]), "r"(a[1]), "r"(a[2]), "r"(a[3]), "r"(b0), "r"(b1));
}

// ---------------- gather span endpoints ----------------
__global__ void gather_kernel(const float* __restrict__ hs, const int* __restrict__ pairs) {
    int bp = blockIdx.x;
    int b = bp / NP;
    int li = pairs[bp * 2 + 0];
    int ri = pairs[bp * 2 + 1];
    const float* lrow = hs + ((long)b * SEQ + li) * DIM;
    const float* rrow = hs + ((long)b * SEQ + ri) * DIM;
    float* gl = g_G + (long)bp * (2 * DIM);
    for (int i = threadIdx.x; i < DIM; i += blockDim.x) {
        gl[i] = lrow[i];
        gl[DIM + i] = rrow[i];
    }
}

// ---------------- generic tiled fp32 GEMM ----------------
template <bool TRANS_B, bool HAS_BIAS>
__global__ void gemm_kernel(const float* __restrict__ A, const float* __restrict__ B,
                            const float* __restrict__ bias, float* __restrict__ C,
                            int M, int N, int K) {
    const int BM = 64, BN = 64, BK = 16;
    __shared__ __align__(16) float As[BK][BM + 4];
    __shared__ __align__(16) float Bs[BK][BN + 4];

    int bm = blockIdx.y * BM;
    int bn = blockIdx.x * BN;
    int tid = threadIdx.x;
    int tx = tid % 16;
    int ty = tid / 16;

    float acc[4][4] = {};

    for (int k0 = 0; k0 < K; k0 += BK) {
        {
            int idx = tid * 4;
            int m = idx / BK;
            int k = idx % BK;
            int gm = bm + m;
            const float* ap = A + (long)gm * K + k0 + k;
#pragma unroll
            for (int i = 0; i < 4; i++) {
                int gk = k0 + k + i;
                As[k + i][m] = (gm < M && gk < K) ? ap[i] : 0.f;
            }
        }
        if (!TRANS_B) {
            int idx = tid * 4;
            int k = idx / BN;
            int n = idx % BN;
            int gk = k0 + k;
            const float* bpr = B + (long)gk * N + bn + n;
#pragma unroll
            for (int i = 0; i < 4; i++) {
                int gn = bn + n + i;
                Bs[k][n + i] = (gk < K && gn < N) ? bpr[i] : 0.f;
            }
        } else {
            int idx = tid * 4;
            int n = idx / BK;
            int k = idx % BK;
            int gn = bn + n;
            const float* bpr = B + (long)gn * K + k0 + k;
#pragma unroll
            for (int i = 0; i < 4; i++) {
                int gk = k0 + k + i;
                Bs[k + i][n] = (gn < N && gk < K) ? bpr[i] : 0.f;
            }
        }
        __syncthreads();

#pragma unroll
        for (int kk = 0; kk < BK; kk++) {
            float4 a4 = *reinterpret_cast<const float4*>(&As[kk][ty * 4]);
            float4 b4 = *reinterpret_cast<const float4*>(&Bs[kk][tx * 4]);
            float a[4] = {a4.x, a4.y, a4.z, a4.w};
            float b[4] = {b4.x, b4.y, b4.z, b4.w};
#pragma unroll
            for (int i = 0; i < 4; i++)
#pragma unroll
                for (int j = 0; j < 4; j++)
                    acc[i][j] = fmaf(a[i], b[j], acc[i][j]);
        }
        __syncthreads();
    }

#pragma unroll
    for (int i = 0; i < 4; i++) {
        int gm = bm + ty * 4 + i;
        if (gm >= M) continue;
#pragma unroll
        for (int j = 0; j < 4; j++) {
            int gn = bn + tx * 4 + j;
            if (gn < N) {
                float v = acc[i][j];
                if (HAS_BIAS) v += bias[gn];
                C[(long)gm * N + gn] = v;
            }
        }
    }
}

// ---------------- exact BERT gelu ----------------
__device__ __forceinline__ float gelu_exact(float x) {
    return 0.5f * x * (1.f + erff(x * 0.70710678118654752f));
}

// ---------------- fused add + gelu + layernorm -> h1 ----------------
__global__ void fuse1_kernel(const float* __restrict__ b1, const float* __restrict__ g1,
                             const float* __restrict__ be1) {
    int row = blockIdx.x;
    int bp = row / SPAN;
    int l = row % SPAN;
    __shared__ float s[DIM];
    __shared__ float red[256];
    int t = threadIdx.x;

    const float* up = g_u + (long)bp * DIM;
    const float* pp = g_posW + (long)l * DIM;

    float local = 0.f;
    for (int i = t; i < DIM; i += 256) {
        float x = up[i] + pp[i] + b1[i];
        float g = gelu_exact(x);
        s[i] = g;
        local += g;
    }
    red[t] = local;
    __syncthreads();
    for (int off = 128; off > 0; off >>= 1) {
        if (t < off) red[t] += red[t + off];
        __syncthreads();
    }
    float mu = red[0] * (1.f / DIM);
    __syncthreads();

    float lv = 0.f;
    for (int i = t; i < DIM; i += 256) {
        float d = s[i] - mu;
        lv += d * d;
    }
    red[t] = lv;
    __syncthreads();
    for (int off = 128; off > 0; off >>= 1) {
        if (t < off) red[t] += red[t + off];
        __syncthreads();
    }
    float rstd = rsqrtf(red[0] * (1.f / DIM) + 1e-12f);

    float* op = g_h1 + (long)row * DIM;
    for (int i = t; i < DIM; i += 256)
        op[i] = (s[i] - mu) * rstd * g1[i] + be1[i];
}

// ---------------- fused gelu + layernorm, in place on g_h2 ----------------
__global__ void fuse2_kernel(const float* __restrict__ g2, const float* __restrict__ be2) {
    int row = blockIdx.x;
    __shared__ float s[DIM];
    __shared__ float red[256];
    int t = threadIdx.x;

    float* rp = g_h2 + (long)row * DIM;
    float local = 0.f;
    for (int i = t; i < DIM; i += 256) {
        float g = gelu_exact(rp[i]);
        s[i] = g;
        local += g;
    }
    red[t] = local;
    __syncthreads();
    for (int off = 128; off > 0; off >>= 1) {
        if (t < off) red[t] += red[t + off];
        __syncthreads();
    }
    float mu = red[0] * (1.f / DIM);
    __syncthreads();

    float lv = 0.f;
    for (int i = t; i < DIM; i += 256) {
        float d = s[i] - mu;
        lv += d * d;
    }
    red[t] = lv;
    __syncthreads();
    for (int off = 128; off > 0; off >>= 1) {
        if (t < off) red[t] += red[t + off];
        __syncthreads();
    }
    float rstd = rsqrtf(red[0] * (1.f / DIM) + 1e-12f);

    for (int i = t; i < DIM; i += 256)
        rp[i] = (s[i] - mu) * rstd * g2[i] + be2[i];
}

// ---------------- split-bf16 conversions (plain row-major) ----------------
__global__ void convA_kernel(const float* __restrict__ src,
                             __nv_bfloat16* __restrict__ hi, __nv_bfloat16* __restrict__ lo) {
    int i = blockIdx.x * blockDim.x + threadIdx.x;
    if (i >= NROWS * EMB) return;
    float x = src[i];
    __nv_bfloat16 h = __float2bfloat16(x);
    hi[i] = h;
    lo[i] = __float2bfloat16(x - __bfloat162float(h));
}
__global__ void convB_kernel(const float* __restrict__ W,
                             __nv_bfloat16* __restrict__ hi, __nv_bfloat16* __restrict__ lo) {
    int i = blockIdx.x * blockDim.x + threadIdx.x;
    if (i >= BROWS * EMB) return;
    int row = i >> 7;
    float x = (row < VOCAB) ? W[i] : 0.f;
    __nv_bfloat16 h = __float2bfloat16(x);
    hi[i] = h;
    lo[i] = __float2bfloat16(x - __bfloat162float(h));
}

// ---------------- decoder: out[5120,30522] = h3 @ Wdec^T via mma.sync split-bf16 ----------------
// CTA tile: 128 M x 256 N x 128 K. 512 threads = 16 warps (4 M x 4 N), warp tile 32x64.
#define DTH 512
#define DEC_SMEM 196608
// smem offsets (bytes): Ahi 0(32K), Alo 32K(32K), Bhi 64K(64K), Blo 128K(64K)

__global__ __launch_bounds__(DTH, 1)
void decoder_mma_kernel(const __nv_bfloat16* __restrict__ Ahi, const __nv_bfloat16* __restrict__ Alo,
                        const __nv_bfloat16* __restrict__ Bhi, const __nv_bfloat16* __restrict__ Blo,
                        float* __restrict__ out) {
    extern __shared__ char sm[];
    uint32_t sb = smem_to_u32(sm);
    const uint32_t SA_HI = 0, SA_LO = 32768, SB_HI = 65536, SB_LO = 131072;

    int tid = threadIdx.x;
    int lane = tid & 31;
    int w = tid >> 5;
    int wm = w >> 2;          // 0..3 (M)
    int wn = w & 3;           // 0..3 (N)
    int nt = blockIdx.x;      // 0..119
    int mt = blockIdx.y;      // 0..39

    // --- async tile loads (row = 256 B = 16 chunks of 16 B; swizzle chunk ^= row&7) ---
    const char* gAhi = (const char*)(Ahi + (size_t)mt * 128 * EMB);
    const char* gAlo = (const char*)(Alo + (size_t)mt * 128 * EMB);
    const char* gBhi = (const char*)(Bhi + (size_t)nt * 256 * EMB);
    const char* gBlo = (const char*)(Blo + (size_t)nt * 256 * EMB);

    auto load_tile = [&](uint32_t dst, const char* src, int rows) {
        int total = rows * 16;
        for (int c = tid; c < total; c += DTH) {
            int r = c >> 4, ch = c & 15;
            uint32_t off = (uint32_t)r * 256 + (uint32_t)((ch ^ (r & 7)) * 16);
            cp_async16(sb + dst + off, src + (size_t)r * 256 + (size_t)ch * 16);
        }
    };
    load_tile(SA_HI, gAhi, 128);
    load_tile(SB_HI, gBhi, 256);
    asm volatile("cp.async.commit_group;" ::: "memory");
    load_tile(SA_LO, gAlo, 128);
    load_tile(SB_LO, gBlo, 256);
    asm volatile("cp.async.commit_group;" ::: "memory");

    float acc[2][8][4] = {};

    int lr = ((lane >> 3) & 1) * 8 + (lane & 7);   // row-within-16 for ldmatrix addr
    int lc = lane >> 4;                            // k-chunk select

    auto compute_term = [&](uint32_t sa, uint32_t sbx) {
#pragma unroll
        for (int ks = 0; ks < 8; ks++) {
            uint32_t a[2][4];
#pragma unroll
            for (int mf = 0; mf < 2; mf++) {
                int r = wm * 32 + mf * 16 + lr;
                int ck = ks * 2 + lc;
                uint32_t addr = sb + sa + (uint32_t)r * 256 + (uint32_t)((ck ^ (r & 7)) * 16);
                ldmx4(a[mf], addr);
            }
            uint32_t bfr[4][4];
#pragma unroll
            for (int nf2 = 0; nf2 < 4; nf2++) {
                int r = wn * 64 + nf2 * 16 + lr;
                int ck = ks * 2 + lc;
                uint32_t addr = sb + sbx + (uint32_t)r * 256 + (uint32_t)((ck ^ (r & 7)) * 16);
                ldmx4(bfr[nf2], addr);
            }
#pragma unroll
            for (int mf = 0; mf < 2; mf++)
#pragma unroll
                for (int nf = 0; nf < 8; nf++)
                    mma_bf16(acc[mf][nf], a[mf], bfr[nf >> 1][nf & 1], bfr[nf >> 1][2 + (nf & 1)]);
        }
    };

    asm volatile("cp.async.wait_group 1;" ::: "memory");
    __syncthreads();
    compute_term(SA_HI, SB_HI);     // hi * hi

    asm volatile("cp.async.wait_group 0;" ::: "memory");
    __syncthreads();
    compute_term(SA_LO, SB_HI);     // lo * hi
    compute_term(SA_HI, SB_LO);     // hi * lo

    // --- epilogue: direct stores ---
#pragma unroll
    for (int mf = 0; mf < 2; mf++) {
        int row = mt * 128 + wm * 32 + mf * 16 + (lane >> 2);
#pragma unroll
        for (int nf = 0; nf < 8; nf++) {
            int col = nt * 256 + wn * 64 + nf * 8 + (lane & 3) * 2;
            if (col < VOCAB) {
                *(float2*)(out + (size_t)row * VOCAB + col) =
                    make_float2(acc[mf][nf][0], acc[mf][nf][1]);
                *(float2*)(out + (size_t)(row + 8) * VOCAB + col) =
                    make_float2(acc[mf][nf][2], acc[mf][nf][3]);
            }
        }
    }
}

// ---------------- launch ----------------
extern "C" void kernel_launch(void* const* d_in, const int* in_sizes, int n_in,
                              void* d_out, int out_size) {
    const float* hs    = (const float*)d_in[0];
    const int*   pairs = (const int*)  d_in[1];
    const float* pos   = (const float*)d_in[2];
    const float* W1    = (const float*)d_in[3];
    const float* b1    = (const float*)d_in[4];
    const float* g1    = (const float*)d_in[5];
    const float* be1   = (const float*)d_in[6];
    const float* W2    = (const float*)d_in[7];
    const float* b2    = (const float*)d_in[8];
    const float* g2    = (const float*)d_in[9];
    const float* be2   = (const float*)d_in[10];
    const float* Wp    = (const float*)d_in[11];
    const float* bpv   = (const float*)d_in[12];
    const float* Wdec  = (const float*)d_in[13];
    float* out = (float*)d_out;

    float *pG, *pu, *pposW, *ph1, *ph2, *ph3;
    __nv_bfloat16 *pAhi, *pAlo, *pBhi, *pBlo;
    cudaGetSymbolAddress((void**)&pG,    g_G);
    cudaGetSymbolAddress((void**)&pu,    g_u);
    cudaGetSymbolAddress((void**)&pposW, g_posW);
    cudaGetSymbolAddress((void**)&ph1,   g_h1);
    cudaGetSymbolAddress((void**)&ph2,   g_h2);
    cudaGetSymbolAddress((void**)&ph3,   g_h3);
    cudaGetSymbolAddress((void**)&pAhi,  g_Ahi);
    cudaGetSymbolAddress((void**)&pAlo,  g_Alo);
    cudaGetSymbolAddress((void**)&pBhi,  g_Bhi);
    cudaGetSymbolAddress((void**)&pBlo,  g_Blo);

    cudaFuncSetAttribute(decoder_mma_kernel, cudaFuncAttributeMaxDynamicSharedMemorySize, DEC_SMEM);

    // 0. Wdec -> split bf16 (independent)
    convB_kernel<<<(BROWS * EMB + 255) / 256, 256>>>(Wdec, pBhi, pBlo);

    // 1. gather span endpoint rows -> G [256, 1536]
    gather_kernel<<<NBP, 256>>>(hs, pairs);

    // 2. u = G @ W1[0:1536,:]
    gemm_kernel<false, false><<<dim3(DIM / 64, NBP / 64), 256>>>(pG, W1, nullptr, pu,
                                                                 NBP, DIM, 2 * DIM);
    // 3. posW = pos_emb @ W1[1536:,:]
    gemm_kernel<false, false><<<dim3(DIM / 64, 1), 256>>>(pos, W1 + (long)2 * DIM * DIM,
                                                          nullptr, pposW, SPAN, DIM, PE);
    // 4. h1 = LN(gelu(u + posW + b1))
    fuse1_kernel<<<NROWS, 256>>>(b1, g1, be1);

    // 5. h2pre = h1 @ W2 + b2
    gemm_kernel<false, true><<<dim3(DIM / 64, NROWS / 64), 256>>>(ph1, W2, b2, ph2,
                                                                  NROWS, DIM, DIM);
    // 6. h2 = LN(gelu(h2pre)) in place
    fuse2_kernel<<<NROWS, 256>>>(g2, be2);

    // 7. h3 = h2 @ Wp + bp
    gemm_kernel<false, true><<<dim3(EMB / 64, NROWS / 64), 256>>>(ph2, Wp, bpv, ph3,
                                                                  NROWS, EMB, DIM);
    // 7b. h3 -> split bf16
    convA_kernel<<<(NROWS * EMB + 255) / 256, 256>>>(ph3, pAhi, pAlo);

    // 8. out = h3 @ Wdec^T via mma.sync split-bf16
    decoder_mma_kernel<<<dim3(NTILE_N, NTILE_M), DTH, DEC_SMEM>>>(pAhi, pAlo, pBhi, pBlo, out);
}